// round 11
// baseline (speedup 1.0000x reference)
#include <cuda_runtime.h>
#include <cuda_fp16.h>
#include <cstdint>

// Problem constants (fixed shapes from reference)
#define BB_   2
#define CC_   64
#define DD_   31
#define HW_   16384                 // H*W = 128*128
#define CS_   507904                // channel stride = D*H*W
#define N_TILES 7936                // B * D * (HW/128)
#define DTILES  3968                // D * (HW/128)
#define GRID_ 444                   // persistent: 3 CTAs/SM * 148 SMs
#define SHH   136                   // H/gate region row stride in HALVES (128 cols + 8 pad)

// SMEM layout (float offsets): w1s[8192] | w2s[4096] | b1s[64] | b2s[64] | Rg[64*136 halves]
#define SM_W1 0
#define SM_W2 8192
#define SM_B1 12288
#define SM_B2 12352
#define SM_R  12416                 // half region: 64*136*2B = 17408B = 4352 floats
#define SM_FLOATS (12416 + 4352)    // 16768 floats = 67072 B -> 3 CTAs/SM: 3*68096 = 204 KB, fits

__device__ __forceinline__ uint32_t f2tf(float f) {
    uint32_t u;
    asm("cvt.rna.tf32.f32 %0, %1;" : "=r"(u) : "f"(f));
    return u;
}
__device__ __forceinline__ float tanha(float v) {
    float r;
    asm("tanh.approx.f32 %0, %1;" : "=f"(r) : "f"(v));
    return r;
}
__device__ __forceinline__ void mma8(float& d0, float& d1, float& d2, float& d3,
                                     uint32_t a0, uint32_t a1, uint32_t a2, uint32_t a3,
                                     uint32_t b0, uint32_t b1) {
    asm("mma.sync.aligned.m16n8k8.row.col.f32.tf32.tf32.f32 "
        "{%0,%1,%2,%3}, {%4,%5,%6,%7}, {%8,%9}, {%0,%1,%2,%3};"
        : "+f"(d0), "+f"(d1), "+f"(d2), "+f"(d3)
        : "r"(a0), "r"(a1), "r"(a2), "r"(a3), "r"(b0), "r"(b1));
}

extern "C" __global__ void __launch_bounds__(128, 3)
ssaf_kernel(const float* __restrict__ x, const float* __restrict__ y,
            const float* __restrict__ w1, const float* __restrict__ b1,
            const float* __restrict__ w2, const float* __restrict__ b2,
            float* __restrict__ out)
{
    extern __shared__ float sm[];
    float*  w1s = sm + SM_W1;
    float*  w2s = sm + SM_W2;
    float*  b1s = sm + SM_B1;
    float*  b2s = sm + SM_B2;
    __half* Rg  = (__half*)(sm + SM_R);   // H between GEMMs, then gates for the epilogue

    const int tid  = threadIdx.x;
    const int wid  = tid >> 5;
    const int lane = tid & 31;
    const int t    = lane & 3;   // k index within fragment
    const int g    = lane >> 2;  // row/col index within fragment

    // ---- Load + tf32-convert weights into smem, pre-swizzled in A-fragment order ----
    // dest index i = ((kk*4 + mm)*32 + lane)*4 + j  ->  one LDS.128 per (kk,mm) per lane
    // frag regs: j=0:(g,t) j=1:(g+8,t) j=2:(g,t+4) j=3:(g+8,t+4)
    for (int i = tid; i < 8192; i += 128) {
        int kk = i >> 9; int rem = i & 511;
        int mm = rem >> 7; int l = (rem >> 2) & 31; int jj = rem & 3;
        int gg = l >> 2, tt = l & 3;
        int m = mm * 16 + gg + (jj & 1) * 8;
        int k = kk * 8 + tt + (jj >> 1) * 4;
        w1s[i] = __uint_as_float(f2tf(w1[m * 128 + k]));
    }
    for (int i = tid; i < 4096; i += 128) {
        int kk = i >> 9; int rem = i & 511;
        int mm = rem >> 7; int l = (rem >> 2) & 31; int jj = rem & 3;
        int gg = l >> 2, tt = l & 3;
        int m = mm * 16 + gg + (jj & 1) * 8;
        int k = kk * 8 + tt + (jj >> 1) * 4;
        w2s[i] = __uint_as_float(f2tf(w2[m * 64 + k]));
    }
    if (tid < 64) { b1s[tid] = b1[tid]; b2s[tid] = b2[tid]; }
    __syncthreads();

    const int wcol = wid * 32;   // warp's position slice within the 128-pos tile

    for (int tile = blockIdx.x; tile < N_TILES; tile += GRID_) {
        const int bb  = tile / DTILES;
        const int rem = tile - bb * DTILES;
        const int dd  = rem >> 7;
        const int hw0 = (rem & 127) << 7;
        const int p0  = hw0 + wcol;
        const size_t slabBase = ((size_t)(bb * CC_) * DD_ + dd) * (size_t)HW_;

        // ---------------- GEMM1: H = tanh(W1 * [x;y] + b1) ----------------
        float acc[4][4][4];
        #pragma unroll
        for (int mm = 0; mm < 4; mm++) {
            const float bv0 = b1s[mm * 16 + g];
            const float bv1 = b1s[mm * 16 + g + 8];
            #pragma unroll
            for (int nt = 0; nt < 4; nt++) {
                acc[mm][nt][0] = bv0; acc[mm][nt][1] = bv0;
                acc[mm][nt][2] = bv1; acc[mm][nt][3] = bv1;
            }
        }

        // x half: k-tiles 0..7 (concat channels 0..63)
        {
            const float* p_lo = x + slabBase + (size_t)t * CS_ + p0 + g;
            const float* p_hi = p_lo + (size_t)4 * CS_;
            #pragma unroll
            for (int kk = 0; kk < 8; kk++) {
                uint32_t bf0[4], bf1[4];
                #pragma unroll
                for (int nt = 0; nt < 4; nt++) {
                    bf0[nt] = f2tf(p_lo[nt * 8]);
                    bf1[nt] = f2tf(p_hi[nt * 8]);
                }
                #pragma unroll
                for (int mm = 0; mm < 4; mm++) {
                    const uint4 a = *(const uint4*)(w1s + ((kk * 4 + mm) * 32 + lane) * 4);
                    #pragma unroll
                    for (int nt = 0; nt < 4; nt++)
                        mma8(acc[mm][nt][0], acc[mm][nt][1], acc[mm][nt][2], acc[mm][nt][3],
                             a.x, a.y, a.z, a.w, bf0[nt], bf1[nt]);
                }
                p_lo += (size_t)8 * CS_;
                p_hi += (size_t)8 * CS_;
            }
        }
        // y half: k-tiles 8..15 (concat channels 64..127)
        {
            const float* p_lo = y + slabBase + (size_t)t * CS_ + p0 + g;
            const float* p_hi = p_lo + (size_t)4 * CS_;
            #pragma unroll
            for (int kk = 8; kk < 16; kk++) {
                uint32_t bf0[4], bf1[4];
                #pragma unroll
                for (int nt = 0; nt < 4; nt++) {
                    bf0[nt] = f2tf(p_lo[nt * 8]);
                    bf1[nt] = f2tf(p_hi[nt * 8]);
                }
                #pragma unroll
                for (int mm = 0; mm < 4; mm++) {
                    const uint4 a = *(const uint4*)(w1s + ((kk * 4 + mm) * 32 + lane) * 4);
                    #pragma unroll
                    for (int nt = 0; nt < 4; nt++)
                        mma8(acc[mm][nt][0], acc[mm][nt][1], acc[mm][nt][2], acc[mm][nt][3],
                             a.x, a.y, a.z, a.w, bf0[nt], bf1[nt]);
                }
                p_lo += (size_t)8 * CS_;
                p_hi += (size_t)8 * CS_;
            }
        }

        // tanh -> store H as half (10-bit mantissa == tf32 precision); warp-private columns
        #pragma unroll
        for (int mm = 0; mm < 4; mm++) {
            const int r0 = mm * 16 + g;
            #pragma unroll
            for (int nt = 0; nt < 4; nt++) {
                const int col = wcol + nt * 8 + 2 * t;
                *(__half2*)(Rg + r0 * SHH + col) =
                    __floats2half2_rn(tanha(acc[mm][nt][0]), tanha(acc[mm][nt][1]));
                *(__half2*)(Rg + (r0 + 8) * SHH + col) =
                    __floats2half2_rn(tanha(acc[mm][nt][2]), tanha(acc[mm][nt][3]));
            }
        }
        __syncwarp();

        // ---------------- GEMM2: U = W2 * H + b2 ----------------
        // half-sourced f32 is tf32-exact: no re-rounding needed on load.
        float acc2[4][4][4];
        #pragma unroll
        for (int mm = 0; mm < 4; mm++) {
            const float bv0 = b2s[mm * 16 + g];
            const float bv1 = b2s[mm * 16 + g + 8];
            #pragma unroll
            for (int nt = 0; nt < 4; nt++) {
                acc2[mm][nt][0] = bv0; acc2[mm][nt][1] = bv0;
                acc2[mm][nt][2] = bv1; acc2[mm][nt][3] = bv1;
            }
        }
        #pragma unroll
        for (int kk = 0; kk < 8; kk++) {
            uint32_t bf0[4], bf1[4];
            #pragma unroll
            for (int nt = 0; nt < 4; nt++) {
                bf0[nt] = __float_as_uint(__half2float(Rg[(kk * 8 + t) * SHH + wcol + nt * 8 + g]));
                bf1[nt] = __float_as_uint(__half2float(Rg[(kk * 8 + t + 4) * SHH + wcol + nt * 8 + g]));
            }
            #pragma unroll
            for (int mm = 0; mm < 4; mm++) {
                const uint4 a = *(const uint4*)(w2s + ((kk * 4 + mm) * 32 + lane) * 4);
                #pragma unroll
                for (int nt = 0; nt < 4; nt++)
                    mma8(acc2[mm][nt][0], acc2[mm][nt][1], acc2[mm][nt][2], acc2[mm][nt][3],
                         a.x, a.y, a.z, a.w, bf0[nt], bf1[nt]);
            }
        }
        __syncwarp();   // all lanes done reading H before gates overwrite the region

        // ---------------- Gates -> Rg (half): sigmoid(u) = 0.5 + 0.5*tanh(0.5u) ----------------
        #pragma unroll
        for (int mm = 0; mm < 4; mm++) {
            #pragma unroll
            for (int nt = 0; nt < 4; nt++) {
                const int col = wcol + nt * 8 + 2 * t;
                #pragma unroll
                for (int half_ = 0; half_ < 2; half_++) {
                    const int r = mm * 16 + g + half_ * 8;
                    const float g0 = 0.5f + 0.5f * tanha(0.5f * acc2[mm][nt][half_ * 2 + 0]);
                    const float g1 = 0.5f + 0.5f * tanha(0.5f * acc2[mm][nt][half_ * 2 + 1]);
                    *(__half2*)(Rg + r * SHH + col) = __floats2half2_rn(g0, g1);
                }
            }
        }
        __syncwarp();

        // ---------------- Epilogue: full-128B-line float4 r/w over warp's 32 positions ----------------
        // lane l handles channel r = 4i + (l>>3), positions wcol + (l&7)*4 .. +3
        #pragma unroll 4
        for (int i = 0; i < 16; i++) {
            const int r  = 4 * i + (lane >> 3);
            const int q4 = (lane & 7) * 4;
            const __half2 gA = *(const __half2*)(Rg + r * SHH + wcol + q4);
            const __half2 gB = *(const __half2*)(Rg + r * SHH + wcol + q4 + 2);
            const float2 gab = __half22float2(gA);
            const float2 gcd = __half22float2(gB);
            const size_t gi = slabBase + (size_t)r * CS_ + hw0 + wcol + q4;
            const float4 xv = *(const float4*)(x + gi);
            const float4 yv = *(const float4*)(y + gi);
            float4 ov;
            ov.x = fmaf(gab.x, yv.x - xv.x, xv.x);
            ov.y = fmaf(gab.y, yv.y - xv.y, xv.y);
            ov.z = fmaf(gcd.x, yv.z - xv.z, xv.z);
            ov.w = fmaf(gcd.y, yv.w - xv.w, xv.w);
            *(float4*)(out + gi) = ov;
        }
        __syncwarp();   // gate reads done before next tile's tanh stores overwrite Rg
    }
}

extern "C" void kernel_launch(void* const* d_in, const int* in_sizes, int n_in,
                              void* d_out, int out_size)
{
    const float* x  = (const float*)d_in[0];
    const float* y  = (const float*)d_in[1];
    const float* w1 = (const float*)d_in[2];
    const float* b1 = (const float*)d_in[3];
    const float* w2 = (const float*)d_in[4];
    const float* b2 = (const float*)d_in[5];
    float* out = (float*)d_out;

    const int smem_bytes = SM_FLOATS * (int)sizeof(float);   // 67072 B
    cudaFuncSetAttribute(ssaf_kernel, cudaFuncAttributeMaxDynamicSharedMemorySize, smem_bytes);
    ssaf_kernel<<<GRID_, 128, smem_bytes>>>(x, y, w1, b1, w2, b2, out);
}

// round 12
// speedup vs baseline: 1.0146x; 1.0146x over previous
#include <cuda_runtime.h>
#include <cuda_fp16.h>
#include <cstdint>

// Problem constants (fixed shapes from reference)
#define BB_   2
#define CC_   64
#define DD_   31
#define HW_   16384                 // H*W = 128*128
#define CS_   507904                // channel stride = D*H*W
#define N_TILES 7936                // B * D * (HW/128)
#define DTILES  3968                // D * (HW/128)
#define GRID_ 296                   // persistent: 2 CTAs/SM * 148 SMs
#define SHH   136                   // H/gate region row stride in HALVES (128 cols + 8 pad)
#define SSTG  40                    // stage row stride (floats): frag banks (8t+g)%32 conflict-free

// SMEM layout (float offsets):
//   w1h: 8192 halves (A-frag swizzled)  = 4096 float slots
//   w2h: 4096 halves                    = 2048 float slots
//   b1, b2: 64 floats each
//   Rg:  64 x 136 halves                = 4352 float slots
//   stage: 4 warps x 16 rows x 40 floats = 2560 float slots
#define SM_W1H 0
#define SM_W2H 4096
#define SM_B1  6144
#define SM_B2  6208
#define SM_R   6272
#define SM_STG 10624
#define SM_FLOATS 13184             // 52736 B/CTA -> 2 CTAs/SM easily fits

__device__ __forceinline__ uint32_t f2tf(float f) {
    uint32_t u;
    asm("cvt.rna.tf32.f32 %0, %1;" : "=r"(u) : "f"(f));
    return u;
}
__device__ __forceinline__ float tanha(float v) {
    float r;
    asm("tanh.approx.f32 %0, %1;" : "=f"(r) : "f"(v));
    return r;
}
__device__ __forceinline__ void mma8(float& d0, float& d1, float& d2, float& d3,
                                     uint32_t a0, uint32_t a1, uint32_t a2, uint32_t a3,
                                     uint32_t b0, uint32_t b1) {
    asm("mma.sync.aligned.m16n8k8.row.col.f32.tf32.tf32.f32 "
        "{%0,%1,%2,%3}, {%4,%5,%6,%7}, {%8,%9}, {%0,%1,%2,%3};"
        : "+f"(d0), "+f"(d1), "+f"(d2), "+f"(d3)
        : "r"(a0), "r"(a1), "r"(a2), "r"(a3), "r"(b0), "r"(b1));
}

// A-fragment from half weights: one LDS.64, halves are tf32-exact in f32.
__device__ __forceinline__ void ldafrag(const __half* wh, int frag, int lane, uint32_t A[4]) {
    const uint2 aw = *(const uint2*)(wh + (frag * 32 + lane) * 4);
    const __half2 ha = *(const __half2*)&aw.x;
    const __half2 hb = *(const __half2*)&aw.y;
    const float2 fa = __half22float2(ha);
    const float2 fb = __half22float2(hb);
    A[0] = __float_as_uint(fa.x); A[1] = __float_as_uint(fa.y);
    A[2] = __float_as_uint(fb.x); A[3] = __float_as_uint(fb.y);
}

extern "C" __global__ void __launch_bounds__(128, 2)
ssaf_kernel(const float* __restrict__ x, const float* __restrict__ y,
            const float* __restrict__ w1, const float* __restrict__ b1,
            const float* __restrict__ w2, const float* __restrict__ b2,
            float* __restrict__ out)
{
    extern __shared__ float sm[];
    __half* w1h = (__half*)(sm + SM_W1H);
    __half* w2h = (__half*)(sm + SM_W2H);
    float*  b1s = sm + SM_B1;
    float*  b2s = sm + SM_B2;
    __half* Rg  = (__half*)(sm + SM_R);   // H between GEMMs, then gates

    const int tid  = threadIdx.x;
    const int wid  = tid >> 5;
    const int lane = tid & 31;
    const int t    = lane & 3;   // k index within fragment
    const int g    = lane >> 2;  // row/col index within fragment
    const int cq   = lane >> 3;  // staging: channel sub-row 0..3
    const int qq   = lane & 7;   // staging: 16B quad within 32 positions
    const int wcol = wid * 32;   // warp's position slice within the 128-pos tile

    float* stg = sm + SM_STG + wid * (16 * SSTG);   // per-warp stage: 16 rows x 40 floats

    // ---- Weights -> smem as half, pre-swizzled in A-fragment order ----
    // dest index i = (frag*32 + lane)*4 + j ; frag regs j=0:(g,t) j=1:(g+8,t) j=2:(g,t+4) j=3:(g+8,t+4)
    for (int i = tid; i < 8192; i += 128) {
        int kk = i >> 9; int rem = i & 511;
        int mm = rem >> 7; int l = (rem >> 2) & 31; int jj = rem & 3;
        int gg = l >> 2, tt = l & 3;
        int m = mm * 16 + gg + (jj & 1) * 8;
        int k = kk * 8 + tt + (jj >> 1) * 4;
        w1h[i] = __float2half(w1[m * 128 + k]);
    }
    for (int i = tid; i < 4096; i += 128) {
        int kk = i >> 9; int rem = i & 511;
        int mm = rem >> 7; int l = (rem >> 2) & 31; int jj = rem & 3;
        int gg = l >> 2, tt = l & 3;
        int m = mm * 16 + gg + (jj & 1) * 8;
        int k = kk * 8 + tt + (jj >> 1) * 4;
        w2h[i] = __float2half(w2[m * 64 + k]);
    }
    if (tid < 64) { b1s[tid] = b1[tid]; b2s[tid] = b2[tid]; }
    __syncthreads();

    for (int tile = blockIdx.x; tile < N_TILES; tile += GRID_) {
        const int bb  = tile / DTILES;
        const int rem = tile - bb * DTILES;
        const int dd  = rem >> 7;
        const int hw0 = (rem & 127) << 7;
        const size_t slabBase = ((size_t)(bb * CC_) * DD_ + dd) * (size_t)HW_;

        // per-lane staging source bases (x/y, this warp's 32 positions)
        const float* xs = x + slabBase + hw0 + wcol + 4 * qq;
        const float* ys = y + slabBase + hw0 + wcol + 4 * qq;

        // chunk s (0..7) = concat channels 16s..16s+15 ; s<4 from x, s>=4 from y
        auto ldchunk = [&](float* dst, int s) {
            const float* bp = ((s < 4) ? xs : ys) + (size_t)((s & 3) * 16 + cq) * CS_;
            #pragma unroll
            for (int j = 0; j < 4; j++) {
                const float4 v = *(const float4*)(bp + (size_t)(4 * j) * CS_);
                dst[4 * j + 0] = v.x; dst[4 * j + 1] = v.y;
                dst[4 * j + 2] = v.z; dst[4 * j + 3] = v.w;
            }
        };

        // ---------------- GEMM1: H = tanh(W1 * [x;y] + b1) ----------------
        float acc[4][4][4];
        #pragma unroll
        for (int mm = 0; mm < 4; mm++) {
            const float bv0 = b1s[mm * 16 + g];
            const float bv1 = b1s[mm * 16 + g + 8];
            #pragma unroll
            for (int nt = 0; nt < 4; nt++) {
                acc[mm][nt][0] = bv0; acc[mm][nt][1] = bv0;
                acc[mm][nt][2] = bv1; acc[mm][nt][3] = bv1;
            }
        }

        float cur[16], nxt[16];
        ldchunk(cur, 0);
        #pragma unroll
        for (int s = 0; s < 8; s++) {
            if (s < 7) ldchunk(nxt, s + 1);

            // stage chunk s: row = 4j+cq (channel within chunk), words 4qq..4qq+3 (positions)
            #pragma unroll
            for (int j = 0; j < 4; j++)
                *(float4*)(stg + (4 * j + cq) * SSTG + 4 * qq) =
                    make_float4(cur[4 * j + 0], cur[4 * j + 1], cur[4 * j + 2], cur[4 * j + 3]);
            __syncwarp();

            // two k-tiles per chunk: kk = 2s + kkL ; rows 8*kkL + t (+4)
            #pragma unroll
            for (int kkL = 0; kkL < 2; kkL++) {
                const int kk = 2 * s + kkL;
                uint32_t bf0[4], bf1[4];
                #pragma unroll
                for (int nt = 0; nt < 4; nt++) {
                    bf0[nt] = f2tf(stg[(8 * kkL + t) * SSTG + g + 8 * nt]);
                    bf1[nt] = f2tf(stg[(8 * kkL + t + 4) * SSTG + g + 8 * nt]);
                }
                #pragma unroll
                for (int mm = 0; mm < 4; mm++) {
                    uint32_t A[4];
                    ldafrag(w1h, kk * 4 + mm, lane, A);
                    #pragma unroll
                    for (int nt = 0; nt < 4; nt++)
                        mma8(acc[mm][nt][0], acc[mm][nt][1], acc[mm][nt][2], acc[mm][nt][3],
                             A[0], A[1], A[2], A[3], bf0[nt], bf1[nt]);
                }
            }
            __syncwarp();   // all lanes done reading stage before next STS overwrites it

            if (s < 7) {
                #pragma unroll
                for (int i2 = 0; i2 < 16; i2++) cur[i2] = nxt[i2];
            }
        }

        // tanh -> store H as half (same 10-bit mantissa as tf32); warp-private columns
        #pragma unroll
        for (int mm = 0; mm < 4; mm++) {
            const int r0 = mm * 16 + g;
            #pragma unroll
            for (int nt = 0; nt < 4; nt++) {
                const int col = wcol + nt * 8 + 2 * t;
                *(__half2*)(Rg + r0 * SHH + col) =
                    __floats2half2_rn(tanha(acc[mm][nt][0]), tanha(acc[mm][nt][1]));
                *(__half2*)(Rg + (r0 + 8) * SHH + col) =
                    __floats2half2_rn(tanha(acc[mm][nt][2]), tanha(acc[mm][nt][3]));
            }
        }
        __syncwarp();

        // ---------------- GEMM2: U = W2 * H + b2 ----------------
        float acc2[4][4][4];
        #pragma unroll
        for (int mm = 0; mm < 4; mm++) {
            const float bv0 = b2s[mm * 16 + g];
            const float bv1 = b2s[mm * 16 + g + 8];
            #pragma unroll
            for (int nt = 0; nt < 4; nt++) {
                acc2[mm][nt][0] = bv0; acc2[mm][nt][1] = bv0;
                acc2[mm][nt][2] = bv1; acc2[mm][nt][3] = bv1;
            }
        }
        #pragma unroll
        for (int kk = 0; kk < 8; kk++) {
            uint32_t bf0[4], bf1[4];
            #pragma unroll
            for (int nt = 0; nt < 4; nt++) {
                bf0[nt] = __float_as_uint(__half2float(Rg[(kk * 8 + t) * SHH + wcol + nt * 8 + g]));
                bf1[nt] = __float_as_uint(__half2float(Rg[(kk * 8 + t + 4) * SHH + wcol + nt * 8 + g]));
            }
            #pragma unroll
            for (int mm = 0; mm < 4; mm++) {
                uint32_t A[4];
                ldafrag(w2h, kk * 4 + mm, lane, A);
                #pragma unroll
                for (int nt = 0; nt < 4; nt++)
                    mma8(acc2[mm][nt][0], acc2[mm][nt][1], acc2[mm][nt][2], acc2[mm][nt][3],
                         A[0], A[1], A[2], A[3], bf0[nt], bf1[nt]);
            }
        }
        __syncwarp();   // all lanes done reading H before gates overwrite the region

        // ---------------- Gates -> Rg (half): sigmoid(u) = 0.5 + 0.5*tanh(0.5u) ----------------
        #pragma unroll
        for (int mm = 0; mm < 4; mm++) {
            #pragma unroll
            for (int nt = 0; nt < 4; nt++) {
                const int col = wcol + nt * 8 + 2 * t;
                #pragma unroll
                for (int half_ = 0; half_ < 2; half_++) {
                    const int r = mm * 16 + g + half_ * 8;
                    const float g0 = 0.5f + 0.5f * tanha(0.5f * acc2[mm][nt][half_ * 2 + 0]);
                    const float g1 = 0.5f + 0.5f * tanha(0.5f * acc2[mm][nt][half_ * 2 + 1]);
                    *(__half2*)(Rg + r * SHH + col) = __floats2half2_rn(g0, g1);
                }
            }
        }
        __syncwarp();

        // ---------------- Epilogue: full-128B-line float4 r/w over warp's 32 positions ----------------
        #pragma unroll 4
        for (int i = 0; i < 16; i++) {
            const int r  = 4 * i + (lane >> 3);
            const int q4 = (lane & 7) * 4;
            const __half2 gA = *(const __half2*)(Rg + r * SHH + wcol + q4);
            const __half2 gB = *(const __half2*)(Rg + r * SHH + wcol + q4 + 2);
            const float2 gab = __half22float2(gA);
            const float2 gcd = __half22float2(gB);
            const size_t gi = slabBase + (size_t)r * CS_ + hw0 + wcol + q4;
            const float4 xv = *(const float4*)(x + gi);
            const float4 yv = *(const float4*)(y + gi);
            float4 ov;
            ov.x = fmaf(gab.x, yv.x - xv.x, xv.x);
            ov.y = fmaf(gab.y, yv.y - xv.y, xv.y);
            ov.z = fmaf(gcd.x, yv.z - xv.z, xv.z);
            ov.w = fmaf(gcd.y, yv.w - xv.w, xv.w);
            *(float4*)(out + gi) = ov;
        }
        __syncwarp();   // gate reads done before next tile overwrites Rg / stage
    }
}

extern "C" void kernel_launch(void* const* d_in, const int* in_sizes, int n_in,
                              void* d_out, int out_size)
{
    const float* x  = (const float*)d_in[0];
    const float* y  = (const float*)d_in[1];
    const float* w1 = (const float*)d_in[2];
    const float* b1 = (const float*)d_in[3];
    const float* w2 = (const float*)d_in[4];
    const float* b2 = (const float*)d_in[5];
    float* out = (float*)d_out;

    const int smem_bytes = SM_FLOATS * (int)sizeof(float);   // 52736 B
    cudaFuncSetAttribute(ssaf_kernel, cudaFuncAttributeMaxDynamicSharedMemorySize, smem_bytes);
    ssaf_kernel<<<GRID_, 128, smem_bytes>>>(x, y, w1, b1, w2, b2, out);
}

// round 14
// speedup vs baseline: 1.0627x; 1.0474x over previous
#include <cuda_runtime.h>
#include <cuda_fp16.h>
#include <cstdint>

// Problem constants (fixed shapes from reference)
#define BB_   2
#define CC_   64
#define DD_   31
#define HW_   16384                 // H*W = 128*128
#define CS_   507904                // channel stride = D*H*W
#define N_TILES 7936                // B * D * (HW/128)
#define DTILES  3968                // D * (HW/128)
#define GRID_ 444                   // persistent: 3 CTAs/SM * 148 SMs
#define SHH   136                   // Rg row stride in halves (128 cols + 8 pad; 68 words)
#define SGH   40                    // stage row stride in halves (32 cols + 8 pad; 20 words)

// SMEM layout (float offsets):
//   w1h 8192 halves (fp16 A-frag swizzled) | w2h 4096 halves | b1,b2 | Rg 64x136 halves | stage 4x640 halves
#define SM_W1H 0                    // -> 4096 float slots
#define SM_W2H 4096                 // -> 2048
#define SM_B1  6144
#define SM_B2  6208
#define SM_R   6272                 // -> 4352
#define SM_STG 10624                // -> 1280
#define SM_FLOATS 11904             // 47616 B/CTA -> 3 CTAs/SM fits

__device__ __forceinline__ float tanha(float v) {
    float r;
    asm("tanh.approx.f32 %0, %1;" : "=f"(r) : "f"(v));
    return r;
}
__device__ __forceinline__ void mma16(float& d0, float& d1, float& d2, float& d3,
                                      uint32_t a0, uint32_t a1, uint32_t a2, uint32_t a3,
                                      uint32_t b0, uint32_t b1) {
    asm("mma.sync.aligned.m16n8k16.row.col.f32.f16.f16.f32 "
        "{%0,%1,%2,%3}, {%4,%5,%6,%7}, {%8,%9}, {%0,%1,%2,%3};"
        : "+f"(d0), "+f"(d1), "+f"(d2), "+f"(d3)
        : "r"(a0), "r"(a1), "r"(a2), "r"(a3), "r"(b0), "r"(b1));
}
__device__ __forceinline__ void ldsm4t(uint32_t& r0, uint32_t& r1, uint32_t& r2, uint32_t& r3,
                                       uint32_t addr) {
    asm volatile("ldmatrix.sync.aligned.m8n8.x4.trans.shared.b16 {%0,%1,%2,%3}, [%4];"
                 : "=r"(r0), "=r"(r1), "=r"(r2), "=r"(r3) : "r"(addr));
}
__device__ __forceinline__ uint32_t h2u(__half2 h) { return *(uint32_t*)&h; }

// A-fragment (m16n8k16): 8 halves/lane stored contiguously at init -> one LDS.128
__device__ __forceinline__ void ldafrag16(const __half* wh, int frag, int lane, uint32_t A[4]) {
    const uint4 v = *(const uint4*)(wh + (frag * 32 + lane) * 8);
    A[0] = v.x; A[1] = v.y; A[2] = v.z; A[3] = v.w;
}

extern "C" __global__ void __launch_bounds__(128, 3)
ssaf_kernel(const float* __restrict__ x, const float* __restrict__ y,
            const float* __restrict__ w1, const float* __restrict__ b1,
            const float* __restrict__ w2, const float* __restrict__ b2,
            float* __restrict__ out)
{
    extern __shared__ float sm[];
    __half* w1h = (__half*)(sm + SM_W1H);
    __half* w2h = (__half*)(sm + SM_W2H);
    float*  b1s = sm + SM_B1;
    float*  b2s = sm + SM_B2;
    __half* Rg  = (__half*)(sm + SM_R);   // H between GEMMs, then gates

    const int tid  = threadIdx.x;
    const int wid  = tid >> 5;
    const int lane = tid & 31;
    const int t    = lane & 3;   // threadID-in-group
    const int g    = lane >> 2;  // groupID
    const int ch8  = lane & 7;   // loader: channel-within-8
    const int oct  = lane >> 3;  // loader: 8-position octet 0..3
    const int wcol = wid * 32;   // warp's position slice

    __half* stgw = (__half*)(sm + SM_STG) + wid * 640;      // per-warp stage (16 x 40 halves)
    const uint32_t smem_u32 = (uint32_t)__cvta_generic_to_shared(sm);
    const uint32_t stg_u = smem_u32 + SM_STG * 4 + wid * 1280;
    const uint32_t rg_u  = smem_u32 + SM_R * 4;

    // ---- Weights -> smem as half, swizzled in m16n8k16 A-frag order ----
    // i = (frag*32 + lane)*8 + j ; frag = kk*4+mm
    // j: reg=j>>1 pairs: m = mm*16 + g + 8*((j>>1)&1) ; k = kk*16 + 2t + (j&1) + 8*(j>>2)
    for (int i = tid; i < 8192; i += 128) {
        int frag = i >> 8; int l = (i >> 3) & 31; int j = i & 7;
        int kk = frag >> 2, mm = frag & 3;
        int m = mm * 16 + (l >> 2) + 8 * ((j >> 1) & 1);
        int k = kk * 16 + 2 * (l & 3) + (j & 1) + 8 * (j >> 2);
        w1h[i] = __float2half(w1[m * 128 + k]);
    }
    for (int i = tid; i < 4096; i += 128) {
        int frag = i >> 8; int l = (i >> 3) & 31; int j = i & 7;
        int kk = frag >> 2, mm = frag & 3;
        int m = mm * 16 + (l >> 2) + 8 * ((j >> 1) & 1);
        int k = kk * 16 + 2 * (l & 3) + (j & 1) + 8 * (j >> 2);
        w2h[i] = __float2half(w2[m * 64 + k]);
    }
    if (tid < 64) { b1s[tid] = b1[tid]; b2s[tid] = b2[tid]; }
    __syncthreads();

    for (int tile = blockIdx.x; tile < N_TILES; tile += GRID_) {
        const int bb  = tile / DTILES;
        const int rem = tile - bb * DTILES;
        const int dd  = rem >> 7;
        const int hw0 = (rem & 127) << 7;
        const size_t slabBase = ((size_t)(bb * CC_) * DD_ + dd) * (size_t)HW_;

        // loader bases: lane covers channel (chunk_ch + r*8 + ch8), positions oct*8..+7
        const float* xs = x + slabBase + hw0 + wcol + oct * 8;
        const float* ys = y + slabBase + hw0 + wcol + oct * 8;

        // chunk s = concat channels 16s..16s+15 == fp16 k-tile s ; s<4 from x, else y
        auto ldchunk = [&](float* dst, int s) {
            const float* bp = ((s < 4) ? xs : ys) + (size_t)((s & 3) * 16 + ch8) * CS_;
            #pragma unroll
            for (int r = 0; r < 2; r++) {
                const float4 v0 = *(const float4*)(bp + (size_t)(8 * r) * CS_);
                const float4 v1 = *(const float4*)(bp + (size_t)(8 * r) * CS_ + 4);
                dst[8 * r + 0] = v0.x; dst[8 * r + 1] = v0.y; dst[8 * r + 2] = v0.z; dst[8 * r + 3] = v0.w;
                dst[8 * r + 4] = v1.x; dst[8 * r + 5] = v1.y; dst[8 * r + 6] = v1.z; dst[8 * r + 7] = v1.w;
            }
        };

        // ---------------- GEMM1: H = tanh(W1 * [x;y] + b1) ----------------
        float acc[4][4][4];
        #pragma unroll
        for (int mm = 0; mm < 4; mm++) {
            const float bv0 = b1s[mm * 16 + g];
            const float bv1 = b1s[mm * 16 + g + 8];
            #pragma unroll
            for (int nt = 0; nt < 4; nt++) {
                acc[mm][nt][0] = bv0; acc[mm][nt][1] = bv0;
                acc[mm][nt][2] = bv1; acc[mm][nt][3] = bv1;
            }
        }

        float cur[16], nxt[16];
        ldchunk(cur, 0);
        #pragma unroll
        for (int s = 0; s < 8; s++) {
            if (s < 7) ldchunk(nxt, s + 1);

            // stage chunk s as half: row = r*8+ch8 (k-local), cols = oct*8..+7 (positions)
            #pragma unroll
            for (int r = 0; r < 2; r++) {
                uint4 pk;
                pk.x = h2u(__floats2half2_rn(cur[8 * r + 0], cur[8 * r + 1]));
                pk.y = h2u(__floats2half2_rn(cur[8 * r + 2], cur[8 * r + 3]));
                pk.z = h2u(__floats2half2_rn(cur[8 * r + 4], cur[8 * r + 5]));
                pk.w = h2u(__floats2half2_rn(cur[8 * r + 6], cur[8 * r + 7]));
                *(uint4*)(stgw + (r * 8 + ch8) * SGH + oct * 8) = pk;
            }
            __syncwarp();

            // B fragments for k-tile s: two x4.trans ops cover n 0-15 and 16-31
            uint32_t B0[4], B1[4];
            const uint32_t rowoff = (uint32_t)((lane & 15) * SGH + 8 * (lane >> 4)) * 2;
            ldsm4t(B0[0], B0[1], B0[2], B0[3], stg_u + rowoff);
            ldsm4t(B1[0], B1[1], B1[2], B1[3], stg_u + rowoff + 32);
            #pragma unroll
            for (int mm = 0; mm < 4; mm++) {
                uint32_t A[4];
                ldafrag16(w1h, s * 4 + mm, lane, A);
                mma16(acc[mm][0][0], acc[mm][0][1], acc[mm][0][2], acc[mm][0][3],
                      A[0], A[1], A[2], A[3], B0[0], B0[1]);
                mma16(acc[mm][1][0], acc[mm][1][1], acc[mm][1][2], acc[mm][1][3],
                      A[0], A[1], A[2], A[3], B0[2], B0[3]);
                mma16(acc[mm][2][0], acc[mm][2][1], acc[mm][2][2], acc[mm][2][3],
                      A[0], A[1], A[2], A[3], B1[0], B1[1]);
                mma16(acc[mm][3][0], acc[mm][3][1], acc[mm][3][2], acc[mm][3][3],
                      A[0], A[1], A[2], A[3], B1[2], B1[3]);
            }
            __syncwarp();   // all lanes done reading stage before next STS

            if (s < 7) {
                #pragma unroll
                for (int i2 = 0; i2 < 16; i2++) cur[i2] = nxt[i2];
            }
        }

        // tanh -> store H as half; D layout of m16n8k16 == m16n8k8 (rows g/g+8, cols 2t,2t+1)
        #pragma unroll
        for (int mm = 0; mm < 4; mm++) {
            const int r0 = mm * 16 + g;
            #pragma unroll
            for (int nt = 0; nt < 4; nt++) {
                const int col = wcol + nt * 8 + 2 * t;
                *(__half2*)(Rg + r0 * SHH + col) =
                    __floats2half2_rn(tanha(acc[mm][nt][0]), tanha(acc[mm][nt][1]));
                *(__half2*)(Rg + (r0 + 8) * SHH + col) =
                    __floats2half2_rn(tanha(acc[mm][nt][2]), tanha(acc[mm][nt][3]));
            }
        }
        __syncwarp();

        // ---------------- GEMM2: U = W2 * H + b2 (4 k-tiles of 16) ----------------
        float acc2[4][4][4];
        #pragma unroll
        for (int mm = 0; mm < 4; mm++) {
            const float bv0 = b2s[mm * 16 + g];
            const float bv1 = b2s[mm * 16 + g + 8];
            #pragma unroll
            for (int nt = 0; nt < 4; nt++) {
                acc2[mm][nt][0] = bv0; acc2[mm][nt][1] = bv0;
                acc2[mm][nt][2] = bv1; acc2[mm][nt][3] = bv1;
            }
        }
        #pragma unroll
        for (int kk = 0; kk < 4; kk++) {
            uint32_t B0[4], B1[4];
            const uint32_t base = rg_u +
                (uint32_t)(((16 * kk + (lane & 15)) * SHH + wcol + 8 * (lane >> 4)) * 2);
            ldsm4t(B0[0], B0[1], B0[2], B0[3], base);
            ldsm4t(B1[0], B1[1], B1[2], B1[3], base + 32);
            #pragma unroll
            for (int mm = 0; mm < 4; mm++) {
                uint32_t A[4];
                ldafrag16(w2h, kk * 4 + mm, lane, A);
                mma16(acc2[mm][0][0], acc2[mm][0][1], acc2[mm][0][2], acc2[mm][0][3],
                      A[0], A[1], A[2], A[3], B0[0], B0[1]);
                mma16(acc2[mm][1][0], acc2[mm][1][1], acc2[mm][1][2], acc2[mm][1][3],
                      A[0], A[1], A[2], A[3], B0[2], B0[3]);
                mma16(acc2[mm][2][0], acc2[mm][2][1], acc2[mm][2][2], acc2[mm][2][3],
                      A[0], A[1], A[2], A[3], B1[0], B1[1]);
                mma16(acc2[mm][3][0], acc2[mm][3][1], acc2[mm][3][2], acc2[mm][3][3],
                      A[0], A[1], A[2], A[3], B1[2], B1[3]);
            }
        }
        __syncwarp();   // H reads complete before gates overwrite the region

        // ---------------- Gates -> Rg (half): sigmoid(u) = 0.5 + 0.5*tanh(0.5u) ----------------
        #pragma unroll
        for (int mm = 0; mm < 4; mm++) {
            #pragma unroll
            for (int nt = 0; nt < 4; nt++) {
                const int col = wcol + nt * 8 + 2 * t;
                #pragma unroll
                for (int half_ = 0; half_ < 2; half_++) {
                    const int r = mm * 16 + g + half_ * 8;
                    const float g0 = 0.5f + 0.5f * tanha(0.5f * acc2[mm][nt][half_ * 2 + 0]);
                    const float g1 = 0.5f + 0.5f * tanha(0.5f * acc2[mm][nt][half_ * 2 + 1]);
                    *(__half2*)(Rg + r * SHH + col) = __floats2half2_rn(g0, g1);
                }
            }
        }
        __syncwarp();

        // ---------------- Epilogue: full-128B-line float4 r/w over warp's 32 positions ----------------
        #pragma unroll 4
        for (int i = 0; i < 16; i++) {
            const int r  = 4 * i + (lane >> 3);
            const int q4 = (lane & 7) * 4;
            const __half2 gA = *(const __half2*)(Rg + r * SHH + wcol + q4);
            const __half2 gB = *(const __half2*)(Rg + r * SHH + wcol + q4 + 2);
            const float2 gab = __half22float2(gA);
            const float2 gcd = __half22float2(gB);
            const size_t gi = slabBase + (size_t)r * CS_ + hw0 + wcol + q4;
            const float4 xv = *(const float4*)(x + gi);
            const float4 yv = *(const float4*)(y + gi);
            float4 ov;
            ov.x = fmaf(gab.x, yv.x - xv.x, xv.x);
            ov.y = fmaf(gab.y, yv.y - xv.y, xv.y);
            ov.z = fmaf(gcd.x, yv.z - xv.z, xv.z);
            ov.w = fmaf(gcd.y, yv.w - xv.w, xv.w);
            *(float4*)(out + gi) = ov;
        }
        __syncwarp();   // gate reads done before next tile overwrites Rg / stage
    }
}

extern "C" void kernel_launch(void* const* d_in, const int* in_sizes, int n_in,
                              void* d_out, int out_size)
{
    const float* x  = (const float*)d_in[0];
    const float* y  = (const float*)d_in[1];
    const float* w1 = (const float*)d_in[2];
    const float* b1 = (const float*)d_in[3];
    const float* w2 = (const float*)d_in[4];
    const float* b2 = (const float*)d_in[5];
    float* out = (float*)d_out;

    const int smem_bytes = SM_FLOATS * (int)sizeof(float);   // 47616 B
    cudaFuncSetAttribute(ssaf_kernel, cudaFuncAttributeMaxDynamicSharedMemorySize, smem_bytes);
    ssaf_kernel<<<GRID_, 128, smem_bytes>>>(x, y, w1, b1, w2, b2, out);
}